// round 1
// baseline (speedup 1.0000x reference)
#include <cuda_runtime.h>

#define BSZ 64
#define NJ  44
#define HS  256
#define REPF 512
#define NLAY 4

// ---------------- persistent device state (no allocations allowed) ----------
__device__ float g_h[BSZ*NJ*HS];
__device__ float g_agg[BSZ*NJ*HS];
__device__ float g_repproj[BSZ*HS];
__device__ float g_x[BSZ*NJ*3];
__device__ float g_x0[BSZ*NJ*3];
__device__ float g_d[BSZ*NJ*NJ];
__device__ float g_d0[BSZ*NJ*NJ];
__device__ float g_cdiff[BSZ*NJ*NJ*3];

__device__ __forceinline__ float silu_f(float x) {
    return x / (1.0f + __expf(-x));
}

// ---------------- rep projection: (64,512) @ (512,256) ---------------------
__global__ __launch_bounds__(256) void k_repproj(const float* __restrict__ rep,
                                                 const float* __restrict__ Wr,
                                                 const float* __restrict__ br) {
    __shared__ float sr[REPF];
    int b = blockIdx.x, c = threadIdx.x;
    sr[c]       = rep[b*REPF + c];
    sr[c + 256] = rep[b*REPF + 256 + c];
    __syncthreads();
    float a0 = 0.f, a1 = 0.f, a2 = 0.f, a3 = 0.f;
    const float* w = Wr + c;
    #pragma unroll 4
    for (int k = 0; k < REPF; k += 4) {
        a0 += sr[k+0] * w[(k+0)*HS];
        a1 += sr[k+1] * w[(k+1)*HS];
        a2 += sr[k+2] * w[(k+2)*HS];
        a3 += sr[k+3] * w[(k+3)*HS];
    }
    g_repproj[b*HS + c] = br[c] + ((a0+a1) + (a2+a3));
}

// ---------------- embedding + x0/x init -------------------------------------
__global__ __launch_bounds__(256) void k_embed(const float* __restrict__ xh,
                                               const float* __restrict__ nm,
                                               const float* __restrict__ tt,
                                               const float* __restrict__ We,
                                               const float* __restrict__ be) {
    int i = blockIdx.x, b = blockIdx.y, c = threadIdx.x;
    __shared__ float f[8];
    float m = nm[b*NJ + i];
    const float* row = xh + (b*NJ + i)*9;
    if (c < 3) {
        float xv = row[c] * m;
        g_x0[(b*NJ+i)*3 + c] = xv;
        g_x [(b*NJ+i)*3 + c] = xv;
    }
    if (c < 6) f[c] = row[3 + c] * m;
    if (c == 6) f[6] = tt[b];
    __syncthreads();
    float acc = be[c] + g_repproj[b*HS + c];
    #pragma unroll
    for (int k = 0; k < 7; k++) acc += f[k] * We[k*HS + c];
    g_h[(b*NJ+i)*HS + c] = acc;
}

// ---------------- pairwise distances (+unit diffs) --------------------------
__global__ __launch_bounds__(256) void k_dist(int which) {
    __shared__ float sx[NJ*3];
    int b = blockIdx.x, t = threadIdx.x;
    const float* xp = which ? g_x : g_x0;
    if (t < NJ*3) sx[t] = xp[b*NJ*3 + t];
    __syncthreads();
    float* dout = which ? g_d : g_d0;
    for (int idx = t; idx < NJ*NJ; idx += blockDim.x) {
        int i = idx / NJ, j = idx % NJ;
        float dx = sx[i*3+0] - sx[j*3+0];
        float dy = sx[i*3+1] - sx[j*3+1];
        float dz = sx[i*3+2] - sx[j*3+2];
        float r = dx*dx + dy*dy + dz*dz;
        dout[b*NJ*NJ + idx] = r;
        if (which) {
            float inv = rsqrtf(r + 1e-8f);
            int o = (b*NJ*NJ + idx)*3;
            g_cdiff[o+0] = dx*inv;
            g_cdiff[o+1] = dy*inv;
            g_cdiff[o+2] = dz*inv;
        }
    }
}

// ---------------- shared edge-MLP core (layers 1 and 2) ----------------------
// sT holds h^T [k][j] on entry (post-barrier); on exit acc2[j] holds the
// PRE-bias layer-2 outputs for all j, and sT holds silu(hidden1)^T.
__device__ __forceinline__ void edge_mlp_core(
    int i, int c,
    const float* __restrict__ W1, const float* __restrict__ b1,
    const float* __restrict__ W2,
    float* sT, const float* sd, const float* sd0,
    float acc2[NJ])
{
    float acc[NJ];
    // h_i contribution (uniform across j)
    float p0 = b1[c], p1 = 0.f, p2 = 0.f, p3 = 0.f;
    {
        const float* w = W1 + c;
        #pragma unroll 4
        for (int k = 0; k < HS; k += 4) {
            p0 += w[(k+0)*HS] * sT[(k+0)*NJ + i];
            p1 += w[(k+1)*HS] * sT[(k+1)*NJ + i];
            p2 += w[(k+2)*HS] * sT[(k+2)*NJ + i];
            p3 += w[(k+3)*HS] * sT[(k+3)*NJ + i];
        }
    }
    float pi = (p0+p1) + (p2+p3);
    float wd  = W1[512*HS + c];
    float wd0 = W1[513*HS + c];
    #pragma unroll
    for (int j = 0; j < NJ; j++) acc[j] = pi + wd*sd[j] + wd0*sd0[j];
    // h_j contribution: register-blocked over all 44 j
    {
        const float* w = W1 + 256*HS + c;
        float wk = w[0];
        for (int k = 0; k < HS; k++) {
            float wn = (k+1 < HS) ? w[(k+1)*HS] : 0.0f;
            const float4* rowp = (const float4*)(sT + k*NJ);
            #pragma unroll
            for (int j4 = 0; j4 < NJ/4; j4++) {
                float4 v = rowp[j4];
                acc[4*j4+0] += wk*v.x;
                acc[4*j4+1] += wk*v.y;
                acc[4*j4+2] += wk*v.z;
                acc[4*j4+3] += wk*v.w;
            }
            wk = wn;
        }
    }
    __syncthreads();  // everyone done reading h^T
    #pragma unroll
    for (int j = 0; j < NJ; j++) sT[c*NJ + j] = silu_f(acc[j]);
    __syncthreads();  // hidden^T visible
    #pragma unroll
    for (int j = 0; j < NJ; j++) acc2[j] = 0.0f;
    {
        const float* w = W2 + c;
        float wk = w[0];
        for (int k = 0; k < HS; k++) {
            float wn = (k+1 < HS) ? w[(k+1)*HS] : 0.0f;
            const float4* rowp = (const float4*)(sT + k*NJ);
            #pragma unroll
            for (int j4 = 0; j4 < NJ/4; j4++) {
                float4 v = rowp[j4];
                acc2[4*j4+0] += wk*v.x;
                acc2[4*j4+1] += wk*v.y;
                acc2[4*j4+2] += wk*v.z;
                acc2[4*j4+3] += wk*v.w;
            }
            wk = wn;
        }
    }
}

// ---------------- fused edge MLP + aggregation -------------------------------
__global__ __launch_bounds__(256, 2) void k_edge(
    const float* __restrict__ W1, const float* __restrict__ b1,
    const float* __restrict__ W2, const float* __restrict__ b2,
    const float* __restrict__ em)
{
    __shared__ __align__(16) float sT[HS*NJ];
    __shared__ float sd[NJ], sd0[NJ], smk[NJ];
    int b = blockIdx.x / NJ, i = blockIdx.x % NJ;
    int c = threadIdx.x;
    const float* hb = g_h + b*NJ*HS;
    for (int idx = c; idx < HS*NJ; idx += 256) {
        int j = idx >> 8, k = idx & 255;
        sT[k*NJ + j] = hb[idx];
    }
    if (c < NJ) {
        int e = (b*NJ + i)*NJ + c;
        sd[c]  = g_d[e];
        sd0[c] = g_d0[e];
        smk[c] = em[e];
    }
    __syncthreads();
    float acc2[NJ];
    edge_mlp_core(i, c, W1, b1, W2, sT, sd, sd0, acc2);
    float bb = b2[c];
    float s = 0.f;
    #pragma unroll
    for (int j = 0; j < NJ; j++) s += silu_f(acc2[j] + bb) * smk[j];
    g_agg[(b*NJ+i)*HS + c] = s * 0.01f;
}

// ---------------- fused node MLP + residual ----------------------------------
__global__ __launch_bounds__(256) void k_node(
    const float* __restrict__ W1, const float* __restrict__ b1,
    const float* __restrict__ W2, const float* __restrict__ b2,
    const float* __restrict__ nm)
{
    __shared__ float sbuf[2*HS];
    __shared__ float shid[HS];
    int bi = blockIdx.x;
    int c = threadIdx.x;
    sbuf[c]       = g_h[bi*HS + c];
    sbuf[256 + c] = g_agg[bi*HS + c];
    __syncthreads();
    float a0=0.f,a1=0.f,a2=0.f,a3=0.f;
    const float* w = W1 + c;
    #pragma unroll 4
    for (int k = 0; k < 2*HS; k += 4) {
        a0 += sbuf[k+0]*w[(k+0)*HS];
        a1 += sbuf[k+1]*w[(k+1)*HS];
        a2 += sbuf[k+2]*w[(k+2)*HS];
        a3 += sbuf[k+3]*w[(k+3)*HS];
    }
    shid[c] = silu_f(b1[c] + ((a0+a1)+(a2+a3)));
    __syncthreads();
    float c0=0.f,c1=0.f,c2=0.f,c3=0.f;
    const float* w2 = W2 + c;
    #pragma unroll 4
    for (int k = 0; k < HS; k += 4) {
        c0 += shid[k+0]*w2[(k+0)*HS];
        c1 += shid[k+1]*w2[(k+1)*HS];
        c2 += shid[k+2]*w2[(k+2)*HS];
        c3 += shid[k+3]*w2[(k+3)*HS];
    }
    float m = nm[bi];
    g_h[bi*HS + c] = (sbuf[c] + b2[c] + ((c0+c1)+(c2+c3))) * m;
}

// ---------------- coord MLP + x update ---------------------------------------
__global__ __launch_bounds__(256, 2) void k_coord(
    const float* __restrict__ W1, const float* __restrict__ b1,
    const float* __restrict__ W2, const float* __restrict__ b2,
    const float* __restrict__ W3,
    const float* __restrict__ em, const float* __restrict__ nm)
{
    __shared__ __align__(16) float sT[HS*NJ];
    __shared__ float sd[NJ], sd0[NJ], smk[NJ], sphi[NJ];
    int b = blockIdx.x / NJ, i = blockIdx.x % NJ;
    int c = threadIdx.x;
    const float* hb = g_h + b*NJ*HS;
    for (int idx = c; idx < HS*NJ; idx += 256) {
        int j = idx >> 8, k = idx & 255;
        sT[k*NJ + j] = hb[idx];
    }
    if (c < NJ) {
        int e = (b*NJ + i)*NJ + c;
        sd[c]  = g_d[e];
        sd0[c] = g_d0[e];
        smk[c] = em[e];
    }
    __syncthreads();
    float acc2[NJ];
    edge_mlp_core(i, c, W1, b1, W2, sT, sd, sd0, acc2);
    float bb = b2[c];
    __syncthreads();  // layer-2 reads of sT done everywhere
    #pragma unroll
    for (int j = 0; j < NJ; j++) sT[c*NJ + j] = silu_f(acc2[j] + bb);
    __syncthreads();
    if (c < NJ) {
        float p0=0.f,p1=0.f,p2=0.f,p3=0.f;
        #pragma unroll 4
        for (int k = 0; k < HS; k += 4) {
            p0 += sT[(k+0)*NJ + c]*W3[k+0];
            p1 += sT[(k+1)*NJ + c]*W3[k+1];
            p2 += sT[(k+2)*NJ + c]*W3[k+2];
            p3 += sT[(k+3)*NJ + c]*W3[k+3];
        }
        sphi[c] = ((p0+p1)+(p2+p3)) * smk[c];
    }
    __syncthreads();
    if (c < 3) {
        float s = 0.f;
        const float* cd = g_cdiff + ((size_t)(b*NJ + i)*NJ)*3 + c;
        #pragma unroll 4
        for (int j = 0; j < NJ; j++) s += cd[j*3] * sphi[j];
        float m = nm[b*NJ + i];
        int xi = (b*NJ + i)*3 + c;
        g_x[xi] = (g_x[xi] + s*0.01f) * m;
    }
}

// ---------------- output head -------------------------------------------------
__global__ __launch_bounds__(256) void k_out(const float* __restrict__ nm,
                                             const float* __restrict__ Wo,
                                             const float* __restrict__ bo,
                                             float* __restrict__ out) {
    int b = blockIdx.x, t = threadIdx.x;
    __shared__ float svel[NJ*3];
    __shared__ float smask[NJ];
    __shared__ float smean[3];
    if (t < NJ) {
        float m = nm[b*NJ + t];
        smask[t] = m;
        #pragma unroll
        for (int d = 0; d < 3; d++)
            svel[t*3+d] = (g_x[(b*NJ+t)*3+d] - g_x0[(b*NJ+t)*3+d]) * m;
    }
    __syncthreads();
    if (t == 0) {
        float s0=0.f,s1=0.f,s2=0.f,n=0.f;
        for (int j = 0; j < NJ; j++) {
            s0 += svel[j*3+0]; s1 += svel[j*3+1]; s2 += svel[j*3+2];
            n  += smask[j];
        }
        smean[0] = s0/n; smean[1] = s1/n; smean[2] = s2/n;
    }
    __syncthreads();
    if (t < NJ) {
        #pragma unroll
        for (int d = 0; d < 3; d++)
            out[(b*NJ+t)*9 + d] = (svel[t*3+d] - smean[d]) * smask[t];
    }
    int w = t >> 5, lane = t & 31;
    for (int i = w; i < NJ; i += 8) {
        float a0=0.f,a1=0.f,a2=0.f,a3=0.f,a4=0.f,a5=0.f;
        const float* hp = g_h + (b*NJ + i)*HS;
        for (int k = lane; k < HS; k += 32) {
            float hv = hp[k];
            const float* wr = Wo + k*7;
            a0 += hv*wr[0]; a1 += hv*wr[1]; a2 += hv*wr[2];
            a3 += hv*wr[3]; a4 += hv*wr[4]; a5 += hv*wr[5];
        }
        #pragma unroll
        for (int off = 16; off > 0; off >>= 1) {
            a0 += __shfl_down_sync(0xffffffffu, a0, off);
            a1 += __shfl_down_sync(0xffffffffu, a1, off);
            a2 += __shfl_down_sync(0xffffffffu, a2, off);
            a3 += __shfl_down_sync(0xffffffffu, a3, off);
            a4 += __shfl_down_sync(0xffffffffu, a4, off);
            a5 += __shfl_down_sync(0xffffffffu, a5, off);
        }
        if (lane == 0) {
            float m = smask[i];
            float* o = out + (b*NJ+i)*9;
            o[3] = (a0 + bo[0]) * m;
            o[4] = (a1 + bo[1]) * m;
            o[5] = (a2 + bo[2]) * m;
            o[6] = (a3 + bo[3]) * m;
            o[7] = (a4 + bo[4]) * m;
            o[8] = (a5 + bo[5]) * m;
        }
    }
}

// ---------------- launch ------------------------------------------------------
extern "C" void kernel_launch(void* const* d_in, const int* in_sizes, int n_in,
                              void* d_out, int out_size) {
    (void)in_sizes; (void)n_in; (void)out_size;
    const float* t       = (const float*)d_in[0];
    const float* xh      = (const float*)d_in[1];
    const float* nm      = (const float*)d_in[2];
    const float* em      = (const float*)d_in[3];
    const float* rep     = (const float*)d_in[4];
    const float* W_embed = (const float*)d_in[5];
    const float* b_embed = (const float*)d_in[6];
    const float* W_rep   = (const float*)d_in[7];
    const float* b_rep   = (const float*)d_in[8];
    const float* We1     = (const float*)d_in[9];
    const float* be1     = (const float*)d_in[10];
    const float* We2     = (const float*)d_in[11];
    const float* be2     = (const float*)d_in[12];
    const float* Wn1     = (const float*)d_in[13];
    const float* bn1     = (const float*)d_in[14];
    const float* Wn2     = (const float*)d_in[15];
    const float* bn2     = (const float*)d_in[16];
    const float* Wc1     = (const float*)d_in[17];
    const float* bc1     = (const float*)d_in[18];
    const float* Wc2     = (const float*)d_in[19];
    const float* bc2     = (const float*)d_in[20];
    const float* Wc3     = (const float*)d_in[21];
    const float* W_out   = (const float*)d_in[22];
    const float* b_out   = (const float*)d_in[23];
    float* out = (float*)d_out;

    k_repproj<<<BSZ, 256>>>(rep, W_rep, b_rep);
    k_embed<<<dim3(NJ, BSZ), 256>>>(xh, nm, t, W_embed, b_embed);
    k_dist<<<BSZ, 256>>>(0);

    int k = 0;
    for (int l = 0; l < NLAY; l++) {
        k_dist<<<BSZ, 256>>>(1);
        for (int s = 0; s < 2; s++, k++) {
            k_edge<<<BSZ*NJ, 256>>>(We1 + (size_t)k*514*HS, be1 + k*HS,
                                    We2 + (size_t)k*HS*HS,  be2 + k*HS, em);
            k_node<<<BSZ*NJ, 256>>>(Wn1 + (size_t)k*512*HS, bn1 + k*HS,
                                    Wn2 + (size_t)k*HS*HS,  bn2 + k*HS, nm);
        }
        k_coord<<<BSZ*NJ, 256>>>(Wc1 + (size_t)l*514*HS, bc1 + l*HS,
                                 Wc2 + (size_t)l*HS*HS,  bc2 + l*HS,
                                 Wc3 + (size_t)l*HS, em, nm);
    }
    k_out<<<BSZ, 256>>>(nm, W_out, b_out, out);
}

// round 2
// speedup vs baseline: 1.8093x; 1.8093x over previous
#include <cuda_runtime.h>

#define BSZ 64
#define NJ  44
#define HS  256
#define REPF 512
#define NLAY 4
#define JJ  22    // nodes per block in pq/node kernels
#define JP  24    // padded (float4-friendly)

// ---------------- persistent device state (no allocations allowed) ----------
__device__ float g_h[BSZ*NJ*HS];
__device__ float g_agg[BSZ*NJ*HS];
__device__ float g_P[BSZ*NJ*HS];
__device__ float g_Q[BSZ*NJ*HS];
__device__ float g_repproj[BSZ*HS];
__device__ float g_x[BSZ*NJ*3];
__device__ float g_x0[BSZ*NJ*3];
__device__ float g_d[BSZ*NJ*NJ];
__device__ float g_d0[BSZ*NJ*NJ];
__device__ float g_cdiff[BSZ*NJ*NJ*3];

__device__ __forceinline__ float silu_f(float x) {
    return x / (1.0f + __expf(-x));
}

// ---------------- rep projection: (64,512) @ (512,256) ---------------------
__global__ __launch_bounds__(256) void k_repproj(const float* __restrict__ rep,
                                                 const float* __restrict__ Wr,
                                                 const float* __restrict__ br) {
    __shared__ float sr[REPF];
    int b = blockIdx.x, c = threadIdx.x;
    sr[c]       = rep[b*REPF + c];
    sr[c + 256] = rep[b*REPF + 256 + c];
    __syncthreads();
    float a0 = 0.f, a1 = 0.f, a2 = 0.f, a3 = 0.f;
    const float* w = Wr + c;
    #pragma unroll 4
    for (int k = 0; k < REPF; k += 4) {
        a0 += sr[k+0] * w[(k+0)*HS];
        a1 += sr[k+1] * w[(k+1)*HS];
        a2 += sr[k+2] * w[(k+2)*HS];
        a3 += sr[k+3] * w[(k+3)*HS];
    }
    g_repproj[b*HS + c] = br[c] + ((a0+a1) + (a2+a3));
}

// ---------------- embedding + x0/x init -------------------------------------
__global__ __launch_bounds__(256) void k_embed(const float* __restrict__ xh,
                                               const float* __restrict__ nm,
                                               const float* __restrict__ tt,
                                               const float* __restrict__ We,
                                               const float* __restrict__ be) {
    int i = blockIdx.x, b = blockIdx.y, c = threadIdx.x;
    __shared__ float f[8];
    float m = nm[b*NJ + i];
    const float* row = xh + (b*NJ + i)*9;
    if (c < 3) {
        float xv = row[c] * m;
        g_x0[(b*NJ+i)*3 + c] = xv;
        g_x [(b*NJ+i)*3 + c] = xv;
    }
    if (c < 6) f[c] = row[3 + c] * m;
    if (c == 6) f[6] = tt[b];
    __syncthreads();
    float acc = be[c] + g_repproj[b*HS + c];
    #pragma unroll
    for (int k = 0; k < 7; k++) acc += f[k] * We[k*HS + c];
    g_h[(b*NJ+i)*HS + c] = acc;
}

// ---------------- pairwise distances (+unit diffs) --------------------------
__global__ __launch_bounds__(256) void k_dist(int which) {
    __shared__ float sx[NJ*3];
    int b = blockIdx.x, t = threadIdx.x;
    const float* xp = which ? g_x : g_x0;
    if (t < NJ*3) sx[t] = xp[b*NJ*3 + t];
    __syncthreads();
    float* dout = which ? g_d : g_d0;
    for (int idx = t; idx < NJ*NJ; idx += blockDim.x) {
        int i = idx / NJ, j = idx % NJ;
        float dx = sx[i*3+0] - sx[j*3+0];
        float dy = sx[i*3+1] - sx[j*3+1];
        float dz = sx[i*3+2] - sx[j*3+2];
        float r = dx*dx + dy*dy + dz*dz;
        dout[b*NJ*NJ + idx] = r;
        if (which) {
            float inv = rsqrtf(r + 1e-8f);
            int o = (b*NJ*NJ + idx)*3;
            g_cdiff[o+0] = dx*inv;
            g_cdiff[o+1] = dy*inv;
            g_cdiff[o+2] = dz*inv;
        }
    }
}

// ---------------- P/Q projection: P = h@W1a + b1, Q = h@W1b ------------------
// grid (BSZ, 2); each block handles 22 nodes.
__global__ __launch_bounds__(256) void k_pq(const float* __restrict__ W1,
                                            const float* __restrict__ b1) {
    __shared__ __align__(16) float shT[HS*JP];  // h transposed [k][j], padded
    int b = blockIdx.x, n0 = blockIdx.y*JJ, c = threadIdx.x;
    for (int idx = c; idx < JJ*HS; idx += 256) {
        int j = idx >> 8, k = idx & 255;
        shT[k*JP + j] = g_h[(b*NJ + n0 + j)*HS + k];
    }
    shT[c*JP + 22] = 0.f;
    shT[c*JP + 23] = 0.f;
    __syncthreads();
    float accP[JP], accQ[JP];
    float bb = b1[c];
    #pragma unroll
    for (int j = 0; j < JP; j++) { accP[j] = bb; accQ[j] = 0.f; }
    const float* wa = W1 + c;
    const float* wb = W1 + 256*HS + c;
    for (int k = 0; k < HS; k++) {
        float fa = wa[k*HS];
        float fb = wb[k*HS];
        const float4* rp = (const float4*)(shT + k*JP);
        #pragma unroll
        for (int j4 = 0; j4 < JP/4; j4++) {
            float4 v = rp[j4];
            accP[4*j4+0] += fa*v.x; accQ[4*j4+0] += fb*v.x;
            accP[4*j4+1] += fa*v.y; accQ[4*j4+1] += fb*v.y;
            accP[4*j4+2] += fa*v.z; accQ[4*j4+2] += fb*v.z;
            accP[4*j4+3] += fa*v.w; accQ[4*j4+3] += fb*v.w;
        }
    }
    #pragma unroll
    for (int j = 0; j < JJ; j++) {
        g_P[(b*NJ + n0 + j)*HS + c] = accP[j];
        g_Q[(b*NJ + n0 + j)*HS + c] = accQ[j];
    }
}

// ---------------- shared edge-MLP core (factored layer 1 + layer 2) ----------
// On entry sbuf holds Q[j][c] (row-major, 44x256). On exit acc2[j] holds the
// PRE-bias layer-2 outputs and sbuf holds silu(hidden1)^T at [c*NJ+j].
__device__ __forceinline__ void edge_core2(
    int c, float pre, float wd, float wd0,
    const float* __restrict__ W2,
    float* sbuf, const float* sd, const float* sd0,
    float acc2[NJ])
{
    float acc[NJ];
    #pragma unroll
    for (int j = 0; j < NJ; j++)
        acc[j] = pre + sbuf[j*HS + c] + wd*sd[j] + wd0*sd0[j];
    __syncthreads();  // everyone done reading Q
    #pragma unroll
    for (int j = 0; j < NJ; j++) sbuf[c*NJ + j] = silu_f(acc[j]);
    __syncthreads();  // hidden^T visible
    #pragma unroll
    for (int j = 0; j < NJ; j++) acc2[j] = 0.0f;
    {
        const float* w = W2 + c;
        float wk = w[0];
        for (int k = 0; k < HS; k++) {
            float wn = (k+1 < HS) ? w[(k+1)*HS] : 0.0f;
            const float4* rowp = (const float4*)(sbuf + k*NJ);
            #pragma unroll
            for (int j4 = 0; j4 < NJ/4; j4++) {
                float4 v = rowp[j4];
                acc2[4*j4+0] += wk*v.x;
                acc2[4*j4+1] += wk*v.y;
                acc2[4*j4+2] += wk*v.z;
                acc2[4*j4+3] += wk*v.w;
            }
            wk = wn;
        }
    }
}

// ---------------- fused edge MLP + aggregation -------------------------------
__global__ __launch_bounds__(256, 2) void k_edge(
    const float* __restrict__ W1,   // only rows 512,513 (wd, wd0) used
    const float* __restrict__ W2, const float* __restrict__ b2,
    const float* __restrict__ em)
{
    __shared__ __align__(16) float sbuf[HS*NJ];
    __shared__ float sd[NJ], sd0[NJ], smk[NJ];
    int b = blockIdx.x / NJ, i = blockIdx.x % NJ;
    int c = threadIdx.x;
    const float* qb = g_Q + b*NJ*HS;
    for (int idx = c; idx < HS*NJ; idx += 256) sbuf[idx] = qb[idx];
    if (c < NJ) {
        int e = (b*NJ + i)*NJ + c;
        sd[c]  = g_d[e];
        sd0[c] = g_d0[e];
        smk[c] = em[e];
    }
    __syncthreads();
    float pre = g_P[(b*NJ + i)*HS + c];
    float wd  = W1[512*HS + c];
    float wd0 = W1[513*HS + c];
    float acc2[NJ];
    edge_core2(c, pre, wd, wd0, W2, sbuf, sd, sd0, acc2);
    float bb = b2[c];
    float s = 0.f;
    #pragma unroll
    for (int j = 0; j < NJ; j++) s += silu_f(acc2[j] + bb) * smk[j];
    g_agg[(b*NJ+i)*HS + c] = s * 0.01f;
}

// ---------------- fused node MLP + residual (22 nodes/block) -----------------
__global__ __launch_bounds__(256) void k_node(
    const float* __restrict__ W1, const float* __restrict__ b1,
    const float* __restrict__ W2, const float* __restrict__ b2,
    const float* __restrict__ nm)
{
    __shared__ __align__(16) float shT[2*HS*JP];  // [h;agg] transposed, padded
    int b = blockIdx.x, n0 = blockIdx.y*JJ, c = threadIdx.x;
    for (int idx = c; idx < JJ*HS; idx += 256) {
        int j = idx >> 8, k = idx & 255;
        shT[k*JP + j]          = g_h[(b*NJ + n0 + j)*HS + k];
        shT[(HS+k)*JP + j]     = g_agg[(b*NJ + n0 + j)*HS + k];
    }
    shT[c*JP + 22] = 0.f;       shT[c*JP + 23] = 0.f;
    shT[(HS+c)*JP + 22] = 0.f;  shT[(HS+c)*JP + 23] = 0.f;
    __syncthreads();
    float hid[JP];
    float bb1 = b1[c];
    #pragma unroll
    for (int j = 0; j < JP; j++) hid[j] = bb1;
    {
        const float* w = W1 + c;
        for (int k = 0; k < 2*HS; k++) {
            float wk = w[k*HS];
            const float4* rp = (const float4*)(shT + k*JP);
            #pragma unroll
            for (int j4 = 0; j4 < JP/4; j4++) {
                float4 v = rp[j4];
                hid[4*j4+0] += wk*v.x;
                hid[4*j4+1] += wk*v.y;
                hid[4*j4+2] += wk*v.z;
                hid[4*j4+3] += wk*v.w;
            }
        }
    }
    __syncthreads();  // done reading inputs; reuse first half for hidden^T
    #pragma unroll
    for (int j = 0; j < JJ; j++) shT[c*JP + j] = silu_f(hid[j]);
    shT[c*JP + 22] = 0.f;
    shT[c*JP + 23] = 0.f;
    __syncthreads();
    float out[JP];
    #pragma unroll
    for (int j = 0; j < JP; j++) out[j] = 0.f;
    {
        const float* w = W2 + c;
        for (int k = 0; k < HS; k++) {
            float wk = w[k*HS];
            const float4* rp = (const float4*)(shT + k*JP);
            #pragma unroll
            for (int j4 = 0; j4 < JP/4; j4++) {
                float4 v = rp[j4];
                out[4*j4+0] += wk*v.x;
                out[4*j4+1] += wk*v.y;
                out[4*j4+2] += wk*v.z;
                out[4*j4+3] += wk*v.w;
            }
        }
    }
    float bb2 = b2[c];
    #pragma unroll
    for (int j = 0; j < JJ; j++) {
        int node = b*NJ + n0 + j;
        float m = nm[node];
        g_h[node*HS + c] = (g_h[node*HS + c] + bb2 + out[j]) * m;
    }
}

// ---------------- coord MLP + x update ---------------------------------------
__global__ __launch_bounds__(256, 2) void k_coord(
    const float* __restrict__ W1,   // only rows 512,513 used
    const float* __restrict__ W2, const float* __restrict__ b2,
    const float* __restrict__ W3,
    const float* __restrict__ em, const float* __restrict__ nm)
{
    __shared__ __align__(16) float sbuf[HS*NJ];
    __shared__ float sd[NJ], sd0[NJ], smk[NJ], sphi[NJ];
    int b = blockIdx.x / NJ, i = blockIdx.x % NJ;
    int c = threadIdx.x;
    const float* qb = g_Q + b*NJ*HS;
    for (int idx = c; idx < HS*NJ; idx += 256) sbuf[idx] = qb[idx];
    if (c < NJ) {
        int e = (b*NJ + i)*NJ + c;
        sd[c]  = g_d[e];
        sd0[c] = g_d0[e];
        smk[c] = em[e];
    }
    __syncthreads();
    float pre = g_P[(b*NJ + i)*HS + c];
    float wd  = W1[512*HS + c];
    float wd0 = W1[513*HS + c];
    float acc2[NJ];
    edge_core2(c, pre, wd, wd0, W2, sbuf, sd, sd0, acc2);
    float bb = b2[c];
    __syncthreads();  // layer-2 reads of sbuf done everywhere
    #pragma unroll
    for (int j = 0; j < NJ; j++) sbuf[c*NJ + j] = silu_f(acc2[j] + bb);
    __syncthreads();
    if (c < NJ) {
        float p0=0.f,p1=0.f,p2=0.f,p3=0.f;
        #pragma unroll 4
        for (int k = 0; k < HS; k += 4) {
            p0 += sbuf[(k+0)*NJ + c]*W3[k+0];
            p1 += sbuf[(k+1)*NJ + c]*W3[k+1];
            p2 += sbuf[(k+2)*NJ + c]*W3[k+2];
            p3 += sbuf[(k+3)*NJ + c]*W3[k+3];
        }
        sphi[c] = ((p0+p1)+(p2+p3)) * smk[c];
    }
    __syncthreads();
    if (c < 3) {
        float s = 0.f;
        const float* cd = g_cdiff + ((size_t)(b*NJ + i)*NJ)*3 + c;
        #pragma unroll 4
        for (int j = 0; j < NJ; j++) s += cd[j*3] * sphi[j];
        float m = nm[b*NJ + i];
        int xi = (b*NJ + i)*3 + c;
        g_x[xi] = (g_x[xi] + s*0.01f) * m;
    }
}

// ---------------- output head -------------------------------------------------
__global__ __launch_bounds__(256) void k_out(const float* __restrict__ nm,
                                             const float* __restrict__ Wo,
                                             const float* __restrict__ bo,
                                             float* __restrict__ out) {
    int b = blockIdx.x, t = threadIdx.x;
    __shared__ float svel[NJ*3];
    __shared__ float smask[NJ];
    __shared__ float smean[3];
    if (t < NJ) {
        float m = nm[b*NJ + t];
        smask[t] = m;
        #pragma unroll
        for (int d = 0; d < 3; d++)
            svel[t*3+d] = (g_x[(b*NJ+t)*3+d] - g_x0[(b*NJ+t)*3+d]) * m;
    }
    __syncthreads();
    if (t == 0) {
        float s0=0.f,s1=0.f,s2=0.f,n=0.f;
        for (int j = 0; j < NJ; j++) {
            s0 += svel[j*3+0]; s1 += svel[j*3+1]; s2 += svel[j*3+2];
            n  += smask[j];
        }
        smean[0] = s0/n; smean[1] = s1/n; smean[2] = s2/n;
    }
    __syncthreads();
    if (t < NJ) {
        #pragma unroll
        for (int d = 0; d < 3; d++)
            out[(b*NJ+t)*9 + d] = (svel[t*3+d] - smean[d]) * smask[t];
    }
    int w = t >> 5, lane = t & 31;
    for (int i = w; i < NJ; i += 8) {
        float a0=0.f,a1=0.f,a2=0.f,a3=0.f,a4=0.f,a5=0.f;
        const float* hp = g_h + (b*NJ + i)*HS;
        for (int k = lane; k < HS; k += 32) {
            float hv = hp[k];
            const float* wr = Wo + k*7;
            a0 += hv*wr[0]; a1 += hv*wr[1]; a2 += hv*wr[2];
            a3 += hv*wr[3]; a4 += hv*wr[4]; a5 += hv*wr[5];
        }
        #pragma unroll
        for (int off = 16; off > 0; off >>= 1) {
            a0 += __shfl_down_sync(0xffffffffu, a0, off);
            a1 += __shfl_down_sync(0xffffffffu, a1, off);
            a2 += __shfl_down_sync(0xffffffffu, a2, off);
            a3 += __shfl_down_sync(0xffffffffu, a3, off);
            a4 += __shfl_down_sync(0xffffffffu, a4, off);
            a5 += __shfl_down_sync(0xffffffffu, a5, off);
        }
        if (lane == 0) {
            float m = smask[i];
            float* o = out + (b*NJ+i)*9;
            o[3] = (a0 + bo[0]) * m;
            o[4] = (a1 + bo[1]) * m;
            o[5] = (a2 + bo[2]) * m;
            o[6] = (a3 + bo[3]) * m;
            o[7] = (a4 + bo[4]) * m;
            o[8] = (a5 + bo[5]) * m;
        }
    }
}

// ---------------- launch ------------------------------------------------------
extern "C" void kernel_launch(void* const* d_in, const int* in_sizes, int n_in,
                              void* d_out, int out_size) {
    (void)in_sizes; (void)n_in; (void)out_size;
    const float* t       = (const float*)d_in[0];
    const float* xh      = (const float*)d_in[1];
    const float* nm      = (const float*)d_in[2];
    const float* em      = (const float*)d_in[3];
    const float* rep     = (const float*)d_in[4];
    const float* W_embed = (const float*)d_in[5];
    const float* b_embed = (const float*)d_in[6];
    const float* W_rep   = (const float*)d_in[7];
    const float* b_rep   = (const float*)d_in[8];
    const float* We1     = (const float*)d_in[9];
    const float* be1     = (const float*)d_in[10];
    const float* We2     = (const float*)d_in[11];
    const float* be2     = (const float*)d_in[12];
    const float* Wn1     = (const float*)d_in[13];
    const float* bn1     = (const float*)d_in[14];
    const float* Wn2     = (const float*)d_in[15];
    const float* bn2     = (const float*)d_in[16];
    const float* Wc1     = (const float*)d_in[17];
    const float* bc1     = (const float*)d_in[18];
    const float* Wc2     = (const float*)d_in[19];
    const float* bc2     = (const float*)d_in[20];
    const float* Wc3     = (const float*)d_in[21];
    const float* W_out   = (const float*)d_in[22];
    const float* b_out   = (const float*)d_in[23];
    float* out = (float*)d_out;

    dim3 g2(BSZ, 2);

    k_repproj<<<BSZ, 256>>>(rep, W_rep, b_rep);
    k_embed<<<dim3(NJ, BSZ), 256>>>(xh, nm, t, W_embed, b_embed);
    k_dist<<<BSZ, 256>>>(0);

    int k = 0;
    for (int l = 0; l < NLAY; l++) {
        k_dist<<<BSZ, 256>>>(1);
        for (int s = 0; s < 2; s++, k++) {
            k_pq<<<g2, 256>>>(We1 + (size_t)k*514*HS, be1 + k*HS);
            k_edge<<<BSZ*NJ, 256>>>(We1 + (size_t)k*514*HS,
                                    We2 + (size_t)k*HS*HS,  be2 + k*HS, em);
            k_node<<<g2, 256>>>(Wn1 + (size_t)k*512*HS, bn1 + k*HS,
                                Wn2 + (size_t)k*HS*HS,  bn2 + k*HS, nm);
        }
        k_pq<<<g2, 256>>>(Wc1 + (size_t)l*514*HS, bc1 + l*HS);
        k_coord<<<BSZ*NJ, 256>>>(Wc1 + (size_t)l*514*HS,
                                 Wc2 + (size_t)l*HS*HS,  bc2 + l*HS,
                                 Wc3 + (size_t)l*HS, em, nm);
    }
    k_out<<<BSZ, 256>>>(nm, W_out, b_out, out);
}

// round 4
// speedup vs baseline: 3.6207x; 2.0012x over previous
#include <cuda_runtime.h>
#include <cstdint>

#define BSZ 64
#define NJ  44
#define HS  256
#define REPF 512
#define NLAY 4
#define JJ  22
#define JP  24

// ---------------- persistent device state ----------------
__device__ float g_h[BSZ*NJ*HS];
__device__ float g_agg[BSZ*NJ*HS];
__device__ float g_P[BSZ*NJ*HS];
__device__ float g_Q[BSZ*NJ*HS];
__device__ float g_repproj[BSZ*HS];
__device__ float g_x[BSZ*NJ*3];
__device__ float g_x0[BSZ*NJ*3];
__device__ float g_d[BSZ*NJ*NJ];
__device__ float g_d0[BSZ*NJ*NJ];
__device__ float g_cdiff[BSZ*NJ*NJ*3];
__device__ float g_W2T[12*HS*HS];   // [m][n][k] = tf32(W2_m[k][n])

__device__ __forceinline__ float silu_f(float x) {
    return x / (1.0f + __expf(-x));
}
__device__ __forceinline__ uint32_t f2tf32(float v) {
    uint32_t u;
    asm("cvt.rna.tf32.f32 %0, %1;" : "=r"(u) : "f"(v));
    return u;
}
__device__ __forceinline__ void mma8(float c[4], uint32_t a0, uint32_t a1,
                                     uint32_t a2, uint32_t a3,
                                     uint32_t b0, uint32_t b1) {
    asm volatile("mma.sync.aligned.m16n8k8.row.col.f32.tf32.tf32.f32 "
        "{%0,%1,%2,%3}, {%4,%5,%6,%7}, {%8,%9}, {%0,%1,%2,%3};"
        : "+f"(c[0]), "+f"(c[1]), "+f"(c[2]), "+f"(c[3])
        : "r"(a0), "r"(a1), "r"(a2), "r"(a3), "r"(b0), "r"(b1));
}

// smem float offsets for k_fused
#define OH    0                     // hid/D tile [48][260]
#define OB    12480                 // B chunk [256][36]
#define OD_   21696                 // d  [48]
#define OD0   21744                 // d0 [48]
#define OMK   21792                 // mask [48]
#define OPS   21840                 // psum [8][48]
#define OPHI  22224                 // phi [48]
#define FUSED_FLOATS 22272
#define FUSED_BYTES  (FUSED_FLOATS*4)

// =====================================================================
// Fused edge/coord MLP. block = (b, i). Layer-1 assembled via FFMA from
// factored P/Q + distance rank-2 terms; layer-2 [48x256]@[256x256] on
// tensor pipe via mma.sync tf32. mode 0: edge->g_agg. mode 1: coord->g_x.
// =====================================================================
__global__ __launch_bounds__(256, 2) void k_fused(
    const float* __restrict__ W1,    // rows 512,513 = wd, wd0
    const float* __restrict__ W2T,   // tf32 bits, [n][k]
    const float* __restrict__ b2,
    const float* __restrict__ em,
    const float* __restrict__ W3,    // coord only
    const float* __restrict__ nm,    // coord only
    int mode)
{
    extern __shared__ float S[];
    int tid = threadIdx.x, warp = tid >> 5, lane = tid & 31;
    int lane4 = lane >> 2, lanem = lane & 3;
    int b = blockIdx.x / NJ, i = blockIdx.x % NJ;
    int c = tid;

    // per-thread channel params
    float pre  = g_P[(b*NJ + i)*HS + c];
    float wdv  = W1[512*HS + c];
    float wd0v = W1[513*HS + c];
    float bb   = b2[c];
    float w3v  = mode ? W3[c] : 0.f;

    if (tid < 48) {
        float dv = 0.f, d0v = 0.f, mv = 0.f;
        if (tid < NJ) {
            int e = (b*NJ + i)*NJ + tid;
            dv = g_d[e]; d0v = g_d0[e]; mv = em[e];
        }
        S[OD_ + tid] = dv; S[OD0 + tid] = d0v; S[OMK + tid] = mv;
    }
    __syncthreads();

    // ---- phase 1: hidden[j][c] = tf32(silu(P_i[c]+Q_j[c]+wd*d_j+wd0*d0_j)) ----
    {
        const float* qp = g_Q + b*NJ*HS + c;
        #pragma unroll 4
        for (int j = 0; j < NJ; j++) {
            float v = pre + qp[j*HS] + wdv*S[OD_ + j] + wd0v*S[OD0 + j];
            S[OH + j*260 + c] = __uint_as_float(f2tf32(silu_f(v)));
        }
        #pragma unroll
        for (int j = NJ; j < 48; j++) S[OH + j*260 + c] = 0.f;
    }

    // ---- phase 2: D = hidden @ W2, tensor pipe, K streamed in chunks of 32 ----
    float acc[3][4][4];
    #pragma unroll
    for (int mt = 0; mt < 3; mt++)
        #pragma unroll
        for (int nt = 0; nt < 4; nt++)
            #pragma unroll
            for (int q = 0; q < 4; q++) acc[mt][nt][q] = 0.f;

    for (int kc = 0; kc < 8; kc++) {
        // cooperative load of B chunk [256n][32k] (already tf32 bits)
        {
            int n = tid >> 3, k4 = (tid & 7) * 4;
            #pragma unroll
            for (int q = 0; q < 8; q++) {
                float4 wv = *(const float4*)&W2T[(n + q*32)*HS + kc*32 + k4];
                *(float4*)&S[OB + (n + q*32)*36 + k4] = wv;
            }
        }
        __syncthreads();
        #pragma unroll
        for (int ks = 0; ks < 4; ks++) {
            uint32_t bf[4][2];
            #pragma unroll
            for (int nt = 0; nt < 4; nt++) {
                int n = warp*32 + nt*8 + lane4;
                bf[nt][0] = __float_as_uint(S[OB + n*36 + ks*8 + lanem]);
                bf[nt][1] = __float_as_uint(S[OB + n*36 + ks*8 + lanem + 4]);
            }
            #pragma unroll
            for (int mt = 0; mt < 3; mt++) {
                int r = mt*16 + lane4;
                int kA = kc*32 + ks*8 + lanem;
                uint32_t a0 = __float_as_uint(S[OH + r*260 + kA]);
                uint32_t a1 = __float_as_uint(S[OH + (r+8)*260 + kA]);
                uint32_t a2 = __float_as_uint(S[OH + r*260 + kA + 4]);
                uint32_t a3 = __float_as_uint(S[OH + (r+8)*260 + kA + 4]);
                #pragma unroll
                for (int nt = 0; nt < 4; nt++)
                    mma8(acc[mt][nt], a0, a1, a2, a3, bf[nt][0], bf[nt][1]);
            }
        }
        __syncthreads();
    }

    // ---- store D into hid buffer (all mma done after last sync) ----
    #pragma unroll
    for (int mt = 0; mt < 3; mt++) {
        int r = mt*16 + lane4;
        #pragma unroll
        for (int nt = 0; nt < 4; nt++) {
            int n = warp*32 + nt*8 + lanem*2;
            S[OH + r*260 + n]       = acc[mt][nt][0];
            S[OH + r*260 + n + 1]   = acc[mt][nt][1];
            S[OH + (r+8)*260 + n]   = acc[mt][nt][2];
            S[OH + (r+8)*260 + n+1] = acc[mt][nt][3];
        }
    }
    __syncthreads();

    // ---- epilogue ----
    if (mode == 0) {
        float s = 0.f;
        #pragma unroll 4
        for (int j = 0; j < NJ; j++)
            s += silu_f(S[OH + j*260 + c] + bb) * S[OMK + j];
        g_agg[(b*NJ + i)*HS + c] = s * 0.01f;
    } else {
        for (int j = 0; j < NJ; j++) {
            float v = silu_f(S[OH + j*260 + c] + bb) * w3v;
            #pragma unroll
            for (int off = 16; off > 0; off >>= 1)
                v += __shfl_xor_sync(0xffffffffu, v, off);
            if (lane == 0) S[OPS + warp*48 + j] = v;
        }
        __syncthreads();
        if (tid < NJ) {
            float ph = 0.f;
            #pragma unroll
            for (int w = 0; w < 8; w++) ph += S[OPS + w*48 + tid];
            S[OPHI + tid] = ph * S[OMK + tid];
        }
        __syncthreads();
        if (tid < 3) {
            float s = 0.f;
            const float* cd = g_cdiff + ((size_t)((b*NJ + i)*NJ))*3 + tid;
            #pragma unroll 4
            for (int j = 0; j < NJ; j++) s += cd[j*3] * S[OPHI + j];
            float m = nm[b*NJ + i];
            int xi = (b*NJ + i)*3 + tid;
            g_x[xi] = (g_x[xi] + s*0.01f) * m;
        }
    }
}

// ---------------- W2 transpose + tf32 convert (12 matrices) ------------------
__global__ void k_transp(const float* __restrict__ We2, const float* __restrict__ Wc2) {
    __shared__ float tile[32][33];
    int m = blockIdx.z;
    const float* src = (m < 8) ? (We2 + (size_t)m*HS*HS) : (Wc2 + (size_t)(m-8)*HS*HS);
    int x0 = blockIdx.x * 32, y0 = blockIdx.y * 32;
    int tx = threadIdx.x, ty = threadIdx.y;
    #pragma unroll
    for (int k = 0; k < 4; k++)
        tile[ty + 8*k][tx] = src[(y0 + ty + 8*k)*HS + x0 + tx];
    __syncthreads();
    #pragma unroll
    for (int k = 0; k < 4; k++)
        g_W2T[(size_t)m*HS*HS + (x0 + ty + 8*k)*HS + y0 + tx] =
            __uint_as_float(f2tf32(tile[tx][ty + 8*k]));
}

// ---------------- rep projection ----------------
__global__ __launch_bounds__(256) void k_repproj(const float* __restrict__ rep,
                                                 const float* __restrict__ Wr,
                                                 const float* __restrict__ br) {
    __shared__ float sr[REPF];
    int b = blockIdx.x, c = threadIdx.x;
    sr[c]       = rep[b*REPF + c];
    sr[c + 256] = rep[b*REPF + 256 + c];
    __syncthreads();
    float a0 = 0.f, a1 = 0.f, a2 = 0.f, a3 = 0.f;
    const float* w = Wr + c;
    #pragma unroll 4
    for (int k = 0; k < REPF; k += 4) {
        a0 += sr[k+0] * w[(k+0)*HS];
        a1 += sr[k+1] * w[(k+1)*HS];
        a2 += sr[k+2] * w[(k+2)*HS];
        a3 += sr[k+3] * w[(k+3)*HS];
    }
    g_repproj[b*HS + c] = br[c] + ((a0+a1) + (a2+a3));
}

// ---------------- embedding + x0/x init ----------------
__global__ __launch_bounds__(256) void k_embed(const float* __restrict__ xh,
                                               const float* __restrict__ nm,
                                               const float* __restrict__ tt,
                                               const float* __restrict__ We,
                                               const float* __restrict__ be) {
    int i = blockIdx.x, b = blockIdx.y, c = threadIdx.x;
    __shared__ float f[8];
    float m = nm[b*NJ + i];
    const float* row = xh + (b*NJ + i)*9;
    if (c < 3) {
        float xv = row[c] * m;
        g_x0[(b*NJ+i)*3 + c] = xv;
        g_x [(b*NJ+i)*3 + c] = xv;
    }
    if (c < 6) f[c] = row[3 + c] * m;
    if (c == 6) f[6] = tt[b];
    __syncthreads();
    float acc = be[c] + g_repproj[b*HS + c];
    #pragma unroll
    for (int k = 0; k < 7; k++) acc += f[k] * We[k*HS + c];
    g_h[(b*NJ+i)*HS + c] = acc;
}

// ---------------- pairwise distances ----------------
__global__ __launch_bounds__(256) void k_dist(int which) {
    __shared__ float sx[NJ*3];
    int b = blockIdx.x, t = threadIdx.x;
    const float* xp = which ? g_x : g_x0;
    if (t < NJ*3) sx[t] = xp[b*NJ*3 + t];
    __syncthreads();
    float* dout = which ? g_d : g_d0;
    for (int idx = t; idx < NJ*NJ; idx += blockDim.x) {
        int i = idx / NJ, j = idx % NJ;
        float dx = sx[i*3+0] - sx[j*3+0];
        float dy = sx[i*3+1] - sx[j*3+1];
        float dz = sx[i*3+2] - sx[j*3+2];
        float r = dx*dx + dy*dy + dz*dz;
        dout[b*NJ*NJ + idx] = r;
        if (which) {
            float inv = rsqrtf(r + 1e-8f);
            int o = (b*NJ*NJ + idx)*3;
            g_cdiff[o+0] = dx*inv;
            g_cdiff[o+1] = dy*inv;
            g_cdiff[o+2] = dz*inv;
        }
    }
}

// ---------------- P/Q projection ----------------
__global__ __launch_bounds__(256) void k_pq(const float* __restrict__ W1,
                                            const float* __restrict__ b1) {
    __shared__ __align__(16) float shT[HS*JP];
    int b = blockIdx.x, n0 = blockIdx.y*JJ, c = threadIdx.x;
    for (int idx = c; idx < JJ*HS; idx += 256) {
        int j = idx >> 8, k = idx & 255;
        shT[k*JP + j] = g_h[(b*NJ + n0 + j)*HS + k];
    }
    shT[c*JP + 22] = 0.f;
    shT[c*JP + 23] = 0.f;
    __syncthreads();
    float accP[JP], accQ[JP];
    float bb = b1[c];
    #pragma unroll
    for (int j = 0; j < JP; j++) { accP[j] = bb; accQ[j] = 0.f; }
    const float* wa = W1 + c;
    const float* wb = W1 + 256*HS + c;
    for (int k = 0; k < HS; k++) {
        float fa = wa[k*HS];
        float fb = wb[k*HS];
        const float4* rp = (const float4*)(shT + k*JP);
        #pragma unroll
        for (int j4 = 0; j4 < JP/4; j4++) {
            float4 v = rp[j4];
            accP[4*j4+0] += fa*v.x; accQ[4*j4+0] += fb*v.x;
            accP[4*j4+1] += fa*v.y; accQ[4*j4+1] += fb*v.y;
            accP[4*j4+2] += fa*v.z; accQ[4*j4+2] += fb*v.z;
            accP[4*j4+3] += fa*v.w; accQ[4*j4+3] += fb*v.w;
        }
    }
    #pragma unroll
    for (int j = 0; j < JJ; j++) {
        g_P[(b*NJ + n0 + j)*HS + c] = accP[j];
        g_Q[(b*NJ + n0 + j)*HS + c] = accQ[j];
    }
}

// ---------------- fused node MLP + residual ----------------
__global__ __launch_bounds__(256) void k_node(
    const float* __restrict__ W1, const float* __restrict__ b1,
    const float* __restrict__ W2, const float* __restrict__ b2,
    const float* __restrict__ nm)
{
    __shared__ __align__(16) float shT[2*HS*JP];
    int b = blockIdx.x, n0 = blockIdx.y*JJ, c = threadIdx.x;
    for (int idx = c; idx < JJ*HS; idx += 256) {
        int j = idx >> 8, k = idx & 255;
        shT[k*JP + j]      = g_h[(b*NJ + n0 + j)*HS + k];
        shT[(HS+k)*JP + j] = g_agg[(b*NJ + n0 + j)*HS + k];
    }
    shT[c*JP + 22] = 0.f;       shT[c*JP + 23] = 0.f;
    shT[(HS+c)*JP + 22] = 0.f;  shT[(HS+c)*JP + 23] = 0.f;
    __syncthreads();
    float hid[JP];
    float bb1 = b1[c];
    #pragma unroll
    for (int j = 0; j < JP; j++) hid[j] = bb1;
    {
        const float* w = W1 + c;
        for (int k = 0; k < 2*HS; k++) {
            float wk = w[k*HS];
            const float4* rp = (const float4*)(shT + k*JP);
            #pragma unroll
            for (int j4 = 0; j4 < JP/4; j4++) {
                float4 v = rp[j4];
                hid[4*j4+0] += wk*v.x;
                hid[4*j4+1] += wk*v.y;
                hid[4*j4+2] += wk*v.z;
                hid[4*j4+3] += wk*v.w;
            }
        }
    }
    __syncthreads();
    #pragma unroll
    for (int j = 0; j < JJ; j++) shT[c*JP + j] = silu_f(hid[j]);
    shT[c*JP + 22] = 0.f;
    shT[c*JP + 23] = 0.f;
    __syncthreads();
    float out[JP];
    #pragma unroll
    for (int j = 0; j < JP; j++) out[j] = 0.f;
    {
        const float* w = W2 + c;
        for (int k = 0; k < HS; k++) {
            float wk = w[k*HS];
            const float4* rp = (const float4*)(shT + k*JP);
            #pragma unroll
            for (int j4 = 0; j4 < JP/4; j4++) {
                float4 v = rp[j4];
                out[4*j4+0] += wk*v.x;
                out[4*j4+1] += wk*v.y;
                out[4*j4+2] += wk*v.z;
                out[4*j4+3] += wk*v.w;
            }
        }
    }
    float bb2 = b2[c];
    #pragma unroll
    for (int j = 0; j < JJ; j++) {
        int node = b*NJ + n0 + j;
        float m = nm[node];
        g_h[node*HS + c] = (g_h[node*HS + c] + bb2 + out[j]) * m;
    }
}

// ---------------- output head ----------------
__global__ __launch_bounds__(256) void k_out(const float* __restrict__ nm,
                                             const float* __restrict__ Wo,
                                             const float* __restrict__ bo,
                                             float* __restrict__ out) {
    int b = blockIdx.x, t = threadIdx.x;
    __shared__ float svel[NJ*3];
    __shared__ float smask[NJ];
    __shared__ float smean[3];
    if (t < NJ) {
        float m = nm[b*NJ + t];
        smask[t] = m;
        #pragma unroll
        for (int d = 0; d < 3; d++)
            svel[t*3+d] = (g_x[(b*NJ+t)*3+d] - g_x0[(b*NJ+t)*3+d]) * m;
    }
    __syncthreads();
    if (t == 0) {
        float s0=0.f,s1=0.f,s2=0.f,n=0.f;
        for (int j = 0; j < NJ; j++) {
            s0 += svel[j*3+0]; s1 += svel[j*3+1]; s2 += svel[j*3+2];
            n  += smask[j];
        }
        smean[0] = s0/n; smean[1] = s1/n; smean[2] = s2/n;
    }
    __syncthreads();
    if (t < NJ) {
        #pragma unroll
        for (int d = 0; d < 3; d++)
            out[(b*NJ+t)*9 + d] = (svel[t*3+d] - smean[d]) * smask[t];
    }
    int w = t >> 5, lane = t & 31;
    for (int i = w; i < NJ; i += 8) {
        float a0=0.f,a1=0.f,a2=0.f,a3=0.f,a4=0.f,a5=0.f;
        const float* hp = g_h + (b*NJ + i)*HS;
        for (int k = lane; k < HS; k += 32) {
            float hv = hp[k];
            const float* wr = Wo + k*7;
            a0 += hv*wr[0]; a1 += hv*wr[1]; a2 += hv*wr[2];
            a3 += hv*wr[3]; a4 += hv*wr[4]; a5 += hv*wr[5];
        }
        #pragma unroll
        for (int off = 16; off > 0; off >>= 1) {
            a0 += __shfl_down_sync(0xffffffffu, a0, off);
            a1 += __shfl_down_sync(0xffffffffu, a1, off);
            a2 += __shfl_down_sync(0xffffffffu, a2, off);
            a3 += __shfl_down_sync(0xffffffffu, a3, off);
            a4 += __shfl_down_sync(0xffffffffu, a4, off);
            a5 += __shfl_down_sync(0xffffffffu, a5, off);
        }
        if (lane == 0) {
            float m = smask[i];
            float* o = out + (b*NJ+i)*9;
            o[3] = (a0 + bo[0]) * m;
            o[4] = (a1 + bo[1]) * m;
            o[5] = (a2 + bo[2]) * m;
            o[6] = (a3 + bo[3]) * m;
            o[7] = (a4 + bo[4]) * m;
            o[8] = (a5 + bo[5]) * m;
        }
    }
}

// ---------------- launch ----------------
extern "C" void kernel_launch(void* const* d_in, const int* in_sizes, int n_in,
                              void* d_out, int out_size) {
    (void)in_sizes; (void)n_in; (void)out_size;
    const float* t       = (const float*)d_in[0];
    const float* xh      = (const float*)d_in[1];
    const float* nm      = (const float*)d_in[2];
    const float* em      = (const float*)d_in[3];
    const float* rep     = (const float*)d_in[4];
    const float* W_embed = (const float*)d_in[5];
    const float* b_embed = (const float*)d_in[6];
    const float* W_rep   = (const float*)d_in[7];
    const float* b_rep   = (const float*)d_in[8];
    const float* We1     = (const float*)d_in[9];
    const float* be1     = (const float*)d_in[10];
    const float* We2     = (const float*)d_in[11];
    const float* be2     = (const float*)d_in[12];
    const float* Wn1     = (const float*)d_in[13];
    const float* bn1     = (const float*)d_in[14];
    const float* Wn2     = (const float*)d_in[15];
    const float* bn2     = (const float*)d_in[16];
    const float* Wc1     = (const float*)d_in[17];
    const float* bc1     = (const float*)d_in[18];
    const float* Wc2     = (const float*)d_in[19];
    const float* bc2     = (const float*)d_in[20];
    const float* Wc3     = (const float*)d_in[21];
    const float* W_out   = (const float*)d_in[22];
    const float* b_out   = (const float*)d_in[23];
    float* out = (float*)d_out;

    static bool attr_done = false;
    if (!attr_done) {
        cudaFuncSetAttribute(k_fused, cudaFuncAttributeMaxDynamicSharedMemorySize,
                             FUSED_BYTES);
        attr_done = true;
    }

    float* W2Tp = nullptr;
    cudaGetSymbolAddress((void**)&W2Tp, g_W2T);

    dim3 g2(BSZ, 2);
    k_transp<<<dim3(8, 8, 12), dim3(32, 8)>>>(We2, Wc2);
    k_repproj<<<BSZ, 256>>>(rep, W_rep, b_rep);
    k_embed<<<dim3(NJ, BSZ), 256>>>(xh, nm, t, W_embed, b_embed);
    k_dist<<<BSZ, 256>>>(0);

    int k = 0;
    for (int l = 0; l < NLAY; l++) {
        k_dist<<<BSZ, 256>>>(1);
        for (int s = 0; s < 2; s++, k++) {
            k_pq<<<g2, 256>>>(We1 + (size_t)k*514*HS, be1 + k*HS);
            k_fused<<<BSZ*NJ, 256, FUSED_BYTES>>>(We1 + (size_t)k*514*HS,
                                                  W2Tp + (size_t)k*HS*HS,
                                                  be2 + k*HS, em, nullptr, nullptr, 0);
            k_node<<<g2, 256>>>(Wn1 + (size_t)k*512*HS, bn1 + k*HS,
                                Wn2 + (size_t)k*HS*HS,  bn2 + k*HS, nm);
        }
        k_pq<<<g2, 256>>>(Wc1 + (size_t)l*514*HS, bc1 + l*HS);
        k_fused<<<BSZ*NJ, 256, FUSED_BYTES>>>(Wc1 + (size_t)l*514*HS,
                                              W2Tp + (size_t)(8 + l)*HS*HS,
                                              bc2 + l*HS, em, Wc3 + (size_t)l*HS, nm, 1);
    }
    k_out<<<BSZ, 256>>>(nm, W_out, b_out, out);
}